// round 8
// baseline (speedup 1.0000x reference)
#include <cuda_runtime.h>

// FMREDynamicDropout: out = x * bernoulli_mask(threefry2x32, keep_prob[c])
// x: [32, 384, 56, 56] fp32, feature_importance: [384] fp32
//
// JAX (threefry_partitionable) semantics, verified bit-exact since R2:
//   key(42) -> (0, 42); ks2 = 0 ^ 42 ^ 0x1BD11BDA = 0x1BD11BF0
//   per element i: hash counter words (0, i); bits[i] = o0 ^ o1
//   mask = bits < (ceil(keep[c] * 2^23) << 9)   (pure uint compare)
//
// R7: genuine pipe steering. R6's __device__ "opaque" constant was never
// stored to, so whole-program ptxas folded it and reverted all IMADs to
// IADD3 (fma stayed ~30%). Here:
//   - ONE / M15 / M26 are made opaque with `asm mov` (outputs of asm cannot
//     be value-propagated), costing 3 registers and no memory traffic.
//   - every add is a literal `mad.lo.u32` -> IMAD (fma pipe).
//   - the 3x rot-15 and 3x rot-26 rounds rotate via `mul.wide.u32` (fma)
//     with the OR+XOR merged into one 3-input LOP3 (alu).
// Per-element target: alu ~38 (14 SHF + 21 LOP3 + epi), fma ~36 (30 IMAD +
// 6 IMAD.WIDE) vs R2's ~53 alu. Alu pipe stops being the lone bottleneck.

#define NCH   384
#define HW    3136u
#define NTOT  38535168u   // 32*384*56*56
#define KS2   0x1BD11BF0u

__device__ unsigned g_thresh[NCH];   // pre-shifted: ceil(keep*2^23) << 9

// ---------------- prep: min/max over feature_importance, integer thresholds ----
__global__ void prep_kernel(const float* __restrict__ fi) {
    int t = threadIdx.x;            // 384 threads
    float v = fi[t];
    float mn = v, mx = v;
    #pragma unroll
    for (int o = 16; o > 0; o >>= 1) {
        mn = fminf(mn, __shfl_xor_sync(0xffffffffu, mn, o));
        mx = fmaxf(mx, __shfl_xor_sync(0xffffffffu, mx, o));
    }
    __shared__ float smn[12], smx[12];
    if ((t & 31) == 0) { smn[t >> 5] = mn; smx[t >> 5] = mx; }
    __syncthreads();
    if (t == 0) {
        float a = smn[0], b = smx[0];
        #pragma unroll
        for (int i = 1; i < 12; i++) { a = fminf(a, smn[i]); b = fmaxf(b, smx[i]); }
        smn[0] = a; smx[0] = b;
    }
    __syncthreads();
    float fmin = smn[0], fmax = smx[0];
    // match reference fp32 op ordering (no fma contraction)
    float scaled = __fdiv_rn(__fsub_rn(v, fmin), __fsub_rn(fmax, fmin));
    float rate   = __fadd_rn(0.1f, __fmul_rn(0.4f, __fsub_rn(1.0f, scaled)));
    float keep   = __fsub_rn(1.0f, rate);
    unsigned Tm = (unsigned)ceilf(__fmul_rn(keep, 8388608.0f));   // <= 0.9*2^23
    g_thresh[t] = Tm << 9;
}

// opaque register: compiler/ptxas cannot value-propagate through asm outputs
__device__ __forceinline__ unsigned opaque_u32(unsigned v) {
    unsigned r;
    asm("mov.b32 %0, %1;" : "=r"(r) : "r"(v));
    return r;
}

// add on fma pipe: x0 = x1 * ONE + x0  (IMAD, multiplier genuinely unknown)
#define ADDF(x0, x1) \
    asm("mad.lo.u32 %0, %1, %2, %0;" : "+r"(x0) : "r"(x1), "r"(ONE))
// injection on fma pipe: x = x * ONE + imm
#define INJF(x, imm) \
    asm("mad.lo.u32 %0, %0, %1, %2;" : "+r"(x) : "r"(ONE), "n"(imm))

// SHF round: add (fma) + funnel-shift (alu) + xor (alu)
#define RS(rot) do { ADDF(x0, x1); \
    x1 = __funnelshift_l(x1, x1, (rot)) ^ x0; } while (0)
// WIDE round: add (fma) + mul.wide (fma) + single LOP3 (lo|hi)^x0 (alu)
#define RW(Mr) do { ADDF(x0, x1); \
    unsigned lo_, hi_; \
    asm("{\n\t.reg .b64 t_;\n\tmul.wide.u32 t_, %2, %3;\n\t" \
        "mov.b64 {%0, %1}, t_;\n\t}" \
        : "=r"(lo_), "=r"(hi_) : "r"(x1), "r"(Mr)); \
    x1 = (lo_ | hi_) ^ x0; } while (0)

// returns o0 ^ o1 for counter words (0, i), key (0, 42)
__device__ __forceinline__ unsigned tf_bits(unsigned i, unsigned ONE,
                                            unsigned M15, unsigned M26) {
    unsigned x1 = i;
    INJF(x1, 42);                           // x1 = i + ks1 (IMAD)
    unsigned x0 = x1;                       // round-1 add: 0 + x1
    x1 = __funnelshift_l(x1, x1, 13) ^ x0;  // round 1  (rot 13)
    RW(M15); RW(M26); RS(6);                // rounds 2-4
    INJF(x0, 42); INJF(x1, (KS2 + 1u));     // inject ks1 / ks2+1
    RS(17); RS(29); RS(16); RS(24);         // rounds 5-8
    INJF(x0, KS2); INJF(x1, 2);             // inject ks2 / ks0+2
    RS(13); RW(M15); RW(M26); RS(6);        // rounds 9-12
    INJF(x1, 45);                           // inject x1 += ks1+3 (x0 += 0)
    RS(17); RS(29); RS(16); RS(24);         // rounds 13-16
    INJF(x0, 42); INJF(x1, (KS2 + 4u));     // inject ks1 / ks2+4
    RS(13); RW(M15); RW(M26); RS(6);        // rounds 17-20
    INJF(x0, KS2); INJF(x1, 5);             // final injection
    return x0 ^ x1;                         // output xor
}

// ---------------- main: 8 consecutive elements (two float4) per thread -------
__global__ void __launch_bounds__(256) drop_kernel(const float* __restrict__ x,
                                                   float* __restrict__ out) {
    const unsigned ONE = opaque_u32(1u);
    const unsigned M15 = opaque_u32(1u << 15);
    const unsigned M26 = opaque_u32(1u << 26);

    unsigned j = (blockIdx.x * 256u + threadIdx.x) * 8u;   // j < NTOT, 8 | HW
    unsigned T = g_thresh[(j / HW) % (unsigned)NCH];       // one channel per thread

    float4 a = *reinterpret_cast<const float4*>(x + j);
    float4 b = *reinterpret_cast<const float4*>(x + j + 4);

    unsigned m[8];
    #pragma unroll
    for (int k = 0; k < 8; k++)
        m[k] = tf_bits(j + (unsigned)k, ONE, M15, M26);

    float4 oa, ob;
    oa.x = (m[0] < T) ? a.x : 0.0f;
    oa.y = (m[1] < T) ? a.y : 0.0f;
    oa.z = (m[2] < T) ? a.z : 0.0f;
    oa.w = (m[3] < T) ? a.w : 0.0f;
    ob.x = (m[4] < T) ? b.x : 0.0f;
    ob.y = (m[5] < T) ? b.y : 0.0f;
    ob.z = (m[6] < T) ? b.z : 0.0f;
    ob.w = (m[7] < T) ? b.w : 0.0f;

    *reinterpret_cast<float4*>(out + j)     = oa;
    *reinterpret_cast<float4*>(out + j + 4) = ob;
}

extern "C" void kernel_launch(void* const* d_in, const int* in_sizes, int n_in,
                              void* d_out, int out_size) {
    const float* x  = (const float*)d_in[0];
    const float* fi = (const float*)d_in[1];
    if (n_in >= 2 && in_sizes[0] == NCH) {   // robust to input ordering
        x  = (const float*)d_in[1];
        fi = (const float*)d_in[0];
    }
    prep_kernel<<<1, NCH>>>(fi);
    // NTOT / 8 elems-per-thread / 256 threads = 18816 blocks, no remainder
    drop_kernel<<<18816, 256>>>(x, (float*)d_out);
}

// round 9
// speedup vs baseline: 1.6453x; 1.6453x over previous
#include <cuda_runtime.h>

// FMREDynamicDropout: out = x * bernoulli_mask(threefry2x32, keep_prob[c])
// x: [32, 384, 56, 56] fp32, feature_importance: [384] fp32
//
// JAX (threefry_partitionable) semantics, verified bit-exact since R2:
//   key(42) -> (0, 42); ks2 = 0 ^ 42 ^ 0x1BD11BDA = 0x1BD11BF0
//   per element i: hash counter words (0, i); bits[i] = o0 ^ o1
//   mask = bits < (ceil(keep[c] * 2^23) << 9)   (pure uint compare)
//
// R8: R2 skeleton + adds steered to the fma pipe via a KERNEL-PARAMETER
// multiplier. History:
//   R2  99.4us: all-SHF, alu pipe 91.8% (the binding pipe, ~54 ops/elem).
//   R3/R4 wide-mul: +1.4-2.4 MOV-tax ops per wide round -> net loss.
//   R6: __device__ ONE const-folded (never written) -> steering no-op.
//   R7: inline-asm steering -> asm operand copies + scheduling barriers,
//       +35% total ops, 164us.
// A launch parameter is opaque by construction (runtime value), costs no
// loads beyond one LDCU->UR, imposes no asm barriers: x1*ONE+x0 MUST emit
// IMAD (fma pipe), and ptxas keeps full scheduling freedom.
// Target: alu ~45/elem (20 SHF + 21 LOP3 + epi), fma ~30 -> ~81us.

#define NCH   384
#define HW    3136u
#define NTOT  38535168u   // 32*384*56*56
#define KS2   0x1BD11BF0u

__device__ unsigned g_thresh[NCH];   // pre-shifted: ceil(keep*2^23) << 9

// ---------------- prep: min/max over feature_importance, integer thresholds ----
__global__ void prep_kernel(const float* __restrict__ fi) {
    int t = threadIdx.x;            // 384 threads
    float v = fi[t];
    float mn = v, mx = v;
    #pragma unroll
    for (int o = 16; o > 0; o >>= 1) {
        mn = fminf(mn, __shfl_xor_sync(0xffffffffu, mn, o));
        mx = fmaxf(mx, __shfl_xor_sync(0xffffffffu, mx, o));
    }
    __shared__ float smn[12], smx[12];
    if ((t & 31) == 0) { smn[t >> 5] = mn; smx[t >> 5] = mx; }
    __syncthreads();
    if (t == 0) {
        float a = smn[0], b = smx[0];
        #pragma unroll
        for (int i = 1; i < 12; i++) { a = fminf(a, smn[i]); b = fmaxf(b, smx[i]); }
        smn[0] = a; smx[0] = b;
    }
    __syncthreads();
    float fmin = smn[0], fmax = smx[0];
    // match reference fp32 op ordering (no fma contraction)
    float scaled = __fdiv_rn(__fsub_rn(v, fmin), __fsub_rn(fmax, fmin));
    float rate   = __fadd_rn(0.1f, __fmul_rn(0.4f, __fsub_rn(1.0f, scaled)));
    float keep   = __fsub_rn(1.0f, rate);
    unsigned Tm = (unsigned)ceilf(__fmul_rn(keep, 8388608.0f));   // <= 0.9*2^23
    g_thresh[t] = Tm << 9;
}

// threefry round: add as IMAD (fma pipe, ONE is a runtime kernel param),
// funnel-shift + xor on alu. Same schedule as R2/R6 (bit-exact verified).
#define TFR(rot) do { x0 = x1 * ONE + x0;                              \
                      x1 = __funnelshift_l(x1, x1, (rot)) ^ x0; } while (0)

// returns o0 ^ o1 for counter words (0, i), key (0, 42)
__device__ __forceinline__ unsigned tf_bits(unsigned i, unsigned ONE) {
    unsigned x1 = i * ONE + 42u;            // counter + ks1        (IMAD)
    unsigned x0 = x1;                       // round-1 add: 0 + x1  (copy)
    x1 = __funnelshift_l(x1, x1, 13) ^ x0;  // round 1  (rot 13)
    TFR(15); TFR(26); TFR(6);               // rounds 2-4
    x0 = x0 * ONE + 42u;                    // inject: x0 += ks1
    x1 = x1 * ONE + (KS2 + 1u);             //         x1 += ks2 + 1
    TFR(17); TFR(29); TFR(16); TFR(24);     // rounds 5-8
    x0 = x0 * ONE + KS2;                    // inject: x0 += ks2
    x1 = x1 * ONE + 2u;                     //         x1 += ks0 + 2
    TFR(13); TFR(15); TFR(26); TFR(6);      // rounds 9-12
    x1 = x1 * ONE + 45u;                    // inject: x1 += ks1+3 (x0 += 0)
    TFR(17); TFR(29); TFR(16); TFR(24);     // rounds 13-16
    x0 = x0 * ONE + 42u;                    // inject: x0 += ks1
    x1 = x1 * ONE + (KS2 + 4u);             //         x1 += ks2 + 4
    TFR(13); TFR(15); TFR(26); TFR(6);      // rounds 17-20
    x0 = x0 * ONE + KS2;                    // final inject x0 += ks2
    x1 = x1 * ONE + 5u;                     //              x1 += ks0 + 5
    return x0 ^ x1;                         // output xor
}

// ---------------- main: 8 consecutive elements (two float4) per thread -------
__global__ void __launch_bounds__(256) drop_kernel(const float* __restrict__ x,
                                                   float* __restrict__ out,
                                                   unsigned ONE) {
    unsigned j = (blockIdx.x * 256u + threadIdx.x) * 8u;   // j < NTOT, 8 | HW
    unsigned T = g_thresh[(j / HW) % (unsigned)NCH];       // one channel per thread

    float4 a = *reinterpret_cast<const float4*>(x + j);
    float4 b = *reinterpret_cast<const float4*>(x + j + 4);

    unsigned m[8];
    #pragma unroll
    for (int k = 0; k < 8; k++)
        m[k] = tf_bits(j + (unsigned)k, ONE);

    float4 oa, ob;
    oa.x = (m[0] < T) ? a.x : 0.0f;
    oa.y = (m[1] < T) ? a.y : 0.0f;
    oa.z = (m[2] < T) ? a.z : 0.0f;
    oa.w = (m[3] < T) ? a.w : 0.0f;
    ob.x = (m[4] < T) ? b.x : 0.0f;
    ob.y = (m[5] < T) ? b.y : 0.0f;
    ob.z = (m[6] < T) ? b.z : 0.0f;
    ob.w = (m[7] < T) ? b.w : 0.0f;

    *reinterpret_cast<float4*>(out + j)     = oa;
    *reinterpret_cast<float4*>(out + j + 4) = ob;
}

extern "C" void kernel_launch(void* const* d_in, const int* in_sizes, int n_in,
                              void* d_out, int out_size) {
    const float* x  = (const float*)d_in[0];
    const float* fi = (const float*)d_in[1];
    if (n_in >= 2 && in_sizes[0] == NCH) {   // robust to input ordering
        x  = (const float*)d_in[1];
        fi = (const float*)d_in[0];
    }
    prep_kernel<<<1, NCH>>>(fi);
    // ONE = 1 passed at runtime: opaque to nvcc/ptxas, forces IMAD adds.
    // NTOT / 8 elems-per-thread / 256 threads = 18816 blocks, no remainder
    drop_kernel<<<18816, 256>>>(x, (float*)d_out, 1u);
}